// round 4
// baseline (speedup 1.0000x reference)
#include <cuda_runtime.h>
#include <cuda_bf16.h>
#include <cstdint>

#define N_NODES 50000
#define N_EDGES 800000
#define FEAT    64
#define CAP     128

__device__ int g_cnt[N_NODES];
__device__ int g_slot[(size_t)N_NODES * CAP];

// ---------------------------------------------------------------------------
// Pass 1: bucket build. One thread per 4 edges (int4 loads).
// ---------------------------------------------------------------------------
__global__ void build_buckets_kernel(const int4* __restrict__ es4,
                                     const int4* __restrict__ ed4,
                                     int*        __restrict__ cnt,
                                     int*        __restrict__ slot)
{
    int t = blockIdx.x * blockDim.x + threadIdx.x;
    if (t >= N_EDGES / 4) return;
    int4 s = __ldg(es4 + t);
    int4 d = __ldg(ed4 + t);
    int p;
    p = atomicAdd(cnt + d.x, 1); if (p < CAP) slot[(size_t)d.x * CAP + p] = s.x;
    p = atomicAdd(cnt + d.y, 1); if (p < CAP) slot[(size_t)d.y * CAP + p] = s.y;
    p = atomicAdd(cnt + d.z, 1); if (p < CAP) slot[(size_t)d.z * CAP + p] = s.z;
    p = atomicAdd(cnt + d.w, 1); if (p < CAP) slot[(size_t)d.w * CAP + p] = s.w;
}

// ---------------------------------------------------------------------------
// Pass 2: one warp per node. Lane c owns float2 chunk c of the 64-float row.
// Gather+sum src rows (slot indices distributed via shfl, inner loop MLP=16),
// then warp-local 8x8 @ 8x8 matmul via smem.
// ---------------------------------------------------------------------------
#define WARPS_PER_BLOCK 8   // 256 threads; 50000/8 = 6250 exact blocks

#define GML(t) do {                                                     \
        int s_ = __shfl_sync(0xffffffffu, idx, j + (t));                \
        float2 v_ = __ldg(src2 + (size_t)s_ * 32 + lane);               \
        acc.x += v_.x; acc.y += v_.y;                                   \
    } while (0)

__global__ void __launch_bounds__(256)
gather_matmul_kernel(const float2* __restrict__ src2,
                     const float2* __restrict__ dst2,
                     const int*    __restrict__ cnt,
                     const int*    __restrict__ slot,
                     float*        __restrict__ out)
{
    __shared__ float S_sm[WARPS_PER_BLOCK][64];
    __shared__ float D_sm[WARPS_PER_BLOCK][64];

    int w    = threadIdx.x >> 5;
    int lane = threadIdx.x & 31;
    int n    = blockIdx.x * WARPS_PER_BLOCK + w;

    int k = __ldg(cnt + n);
    if (k > CAP) k = CAP;
    const int* sb = slot + (size_t)n * CAP;

    float2 acc = make_float2(0.f, 0.f);

    for (int b = 0; b < k; b += 32) {
        int kb = k - b; if (kb > 32) kb = 32;
        // Coalesced batch load of up to 32 slot indices; lanes >= kb clamp to 0
        // (value unused — shfl only pulls lanes < kb).
        int idx = __ldg(sb + b + (lane < kb ? lane : 0));

        int j = 0;
        for (; j + 16 <= kb; j += 16) {     // bulk: 16 independent row loads
            GML(0);  GML(1);  GML(2);  GML(3);
            GML(4);  GML(5);  GML(6);  GML(7);
            GML(8);  GML(9);  GML(10); GML(11);
            GML(12); GML(13); GML(14); GML(15);
        }
        for (; j + 4 <= kb; j += 4) {
            GML(0); GML(1); GML(2); GML(3);
        }
        for (; j < kb; ++j) {
            GML(0);
        }
    }

    // Stash S row and dst row, warp-local.
    S_sm[w][2 * lane]     = acc.x;
    S_sm[w][2 * lane + 1] = acc.y;
    float2 d = __ldg(dst2 + (size_t)n * 32 + lane);
    D_sm[w][2 * lane]     = d.x;
    D_sm[w][2 * lane + 1] = d.y;
    __syncwarp();

    // out[i][j] = sum_p S[i][p] * D[p][j] / sqrt(8)
    // lane -> (i = lane>>2, columns jp..jp+1 with jp = (lane&3)*2); flat offset = 2*lane.
    int i  = lane >> 2;
    int jp = (lane & 3) * 2;
    float o0 = 0.f, o1 = 0.f;
    #pragma unroll
    for (int p = 0; p < 8; ++p) {
        float a = S_sm[w][i * 8 + p];
        o0 = fmaf(a, D_sm[w][p * 8 + jp],     o0);
        o1 = fmaf(a, D_sm[w][p * 8 + jp + 1], o1);
    }
    const float inv = 0.3535533905932737622f;  // 1/sqrt(8)
    reinterpret_cast<float2*>(out + (size_t)n * FEAT)[lane] =
        make_float2(o0 * inv, o1 * inv);
}

extern "C" void kernel_launch(void* const* d_in, const int* in_sizes, int n_in,
                              void* d_out, int out_size)
{
    const float* src_feat = (const float*)d_in[0];
    const float* dst_feat = (const float*)d_in[1];
    const int*   edge_src = (const int*)d_in[2];
    const int*   edge_dst = (const int*)d_in[3];
    float*       out      = (float*)d_out;

    void* cnt_ptr  = nullptr;
    void* slot_ptr = nullptr;
    cudaGetSymbolAddress(&cnt_ptr, g_cnt);
    cudaGetSymbolAddress(&slot_ptr, g_slot);

    cudaMemsetAsync(cnt_ptr, 0, (size_t)N_NODES * sizeof(int), 0);

    {
        int threads = 256;
        int work    = N_EDGES / 4;                 // 200000
        int blocks  = (work + threads - 1) / threads;
        build_buckets_kernel<<<blocks, threads>>>(
            reinterpret_cast<const int4*>(edge_src),
            reinterpret_cast<const int4*>(edge_dst),
            (int*)cnt_ptr, (int*)slot_ptr);
    }
    {
        int threads = WARPS_PER_BLOCK * 32;        // 256
        int blocks  = N_NODES / WARPS_PER_BLOCK;   // 6250 exact
        gather_matmul_kernel<<<blocks, threads>>>(
            reinterpret_cast<const float2*>(src_feat),
            reinterpret_cast<const float2*>(dst_feat),
            (const int*)cnt_ptr, (const int*)slot_ptr, out);
    }
}